// round 2
// baseline (speedup 1.0000x reference)
#include <cuda_runtime.h>
#include <cuda_fp16.h>
#include <stdint.h>

#define NROWS 16384

// ---------------- scratch (device globals; no allocation allowed) ----------------
__device__ float  g_X [NROWS * 128];   // layer output / next-layer input (fp32)
__device__ __half g_G [NROWS * 64];    // graph-learn projection (fp16)
__device__ float  g_SQ[NROWS];         // |g_i|^2 from fp16-rounded g
__device__ __half g_H [NROWS * 128];   // gnn projection (fp16)
__device__ __half g_HR[NROWS * 128];   // fp32-fp16 residual of H (for diag correction)

// ---------------- mma / ldmatrix helpers ----------------
__device__ __forceinline__ void mma_16816(float (&c)[4], const uint32_t (&a)[4],
                                          uint32_t b0, uint32_t b1) {
    asm volatile(
        "mma.sync.aligned.m16n8k16.row.col.f32.f16.f16.f32 "
        "{%0,%1,%2,%3},{%4,%5,%6,%7},{%8,%9},{%0,%1,%2,%3};\n"
        : "+f"(c[0]), "+f"(c[1]), "+f"(c[2]), "+f"(c[3])
        : "r"(a[0]), "r"(a[1]), "r"(a[2]), "r"(a[3]), "r"(b0), "r"(b1));
}

__device__ __forceinline__ void ldsm4(uint32_t &r0, uint32_t &r1, uint32_t &r2, uint32_t &r3,
                                      uint32_t addr) {
    asm volatile("ldmatrix.sync.aligned.m8n8.x4.shared.b16 {%0,%1,%2,%3},[%4];\n"
                 : "=r"(r0), "=r"(r1), "=r"(r2), "=r"(r3) : "r"(addr));
}

__device__ __forceinline__ void ldsm4t(uint32_t &r0, uint32_t &r1, uint32_t &r2, uint32_t &r3,
                                       uint32_t addr) {
    asm volatile("ldmatrix.sync.aligned.m8n8.x4.trans.shared.b16 {%0,%1,%2,%3},[%4];\n"
                 : "=r"(r0), "=r"(r1), "=r"(r2), "=r"(r3) : "r"(addr));
}

__device__ __forceinline__ float sigmoid_fast(float x) {
    // 1/(1+e^-x): MUFU.EX2 + MUFU.RCP (approx div), rel err ~1e-6 — far below tolerance
    return __fdividef(1.0f, 1.0f + __expf(-x));
}

// ---------------- projection kernels ----------------
// X[N,128] @ W[128,DOUT] + B.  GMODE: relu -> fp16 G + sq(|g16|^2).
// !GMODE: fp16 H + fp16 residual (h32 - h16).
template<int DOUT, bool GMODE>
__global__ __launch_bounds__(256) void proj_kernel(
    const float* __restrict__ X, const float* __restrict__ W, const float* __restrict__ B,
    __half* __restrict__ outh, __half* __restrict__ outres, float* __restrict__ sq)
{
    constexpr int CS = DOUT / 32;
    __shared__ __align__(16) float Xs[32 * 132];
    __shared__ __align__(16) float Ws[32 * DOUT];

    const int tid  = threadIdx.x;
    const int lane = tid & 31;
    const int wy   = tid >> 5;                 // 0..7
    const int rowbase = blockIdx.x * 32;

    // load X tile [32][128] (padded pitch 132 for alignment)
    #pragma unroll
    for (int i = tid; i < 32 * 32; i += 256) {
        int r = i >> 5, c = i & 31;
        ((float4*)(Xs + r * 132))[c] =
            ((const float4*)(X + (size_t)(rowbase + r) * 128))[c];
    }

    float acc[4][CS];
    #pragma unroll
    for (int rs = 0; rs < 4; rs++)
        #pragma unroll
        for (int cs = 0; cs < CS; cs++) acc[rs][cs] = 0.f;

    for (int kc = 0; kc < 128; kc += 32) {
        __syncthreads();
        #pragma unroll
        for (int i = tid; i < 32 * DOUT / 4; i += 256)
            ((float4*)Ws)[i] = ((const float4*)(W + (size_t)kc * DOUT))[i];
        __syncthreads();

        #pragma unroll
        for (int k = 0; k < 32; k++) {
            float wv[CS];
            #pragma unroll
            for (int cs = 0; cs < CS; cs++) wv[cs] = Ws[k * DOUT + lane + cs * 32];
            #pragma unroll
            for (int rs = 0; rs < 4; rs++) {
                float xv = Xs[(wy + rs * 8) * 132 + kc + k];
                #pragma unroll
                for (int cs = 0; cs < CS; cs++) acc[rs][cs] = fmaf(xv, wv[cs], acc[rs][cs]);
            }
        }
    }

    #pragma unroll
    for (int rs = 0; rs < 4; rs++) {
        int row = rowbase + wy + rs * 8;
        float ssq = 0.f;
        #pragma unroll
        for (int cs = 0; cs < CS; cs++) {
            int col = lane + cs * 32;
            float v = acc[rs][cs] + B[col];
            if (GMODE) v = fmaxf(v, 0.f);
            __half h = __float2half_rn(v);
            outh[(size_t)row * DOUT + col] = h;
            float vh = __half2float(h);
            if (GMODE) ssq += vh * vh;
            else       outres[(size_t)row * DOUT + col] = __float2half_rn(v - vh);
        }
        if (GMODE) {
            #pragma unroll
            for (int off = 16; off; off >>= 1) ssq += __shfl_xor_sync(0xffffffffu, ssq, off);
            if (lane == 0) sq[row] = ssq;
        }
    }
}

// ---------------- fused sigmoid-attention kernel ----------------
// out_i = sum_j sigmoid(t*(2 g_i.g_j - sq_i - sq_j) + th) * h_j  /  rowsum
// BM=128 rows per CTA (8 warps x 16), BN=64 keys per iteration.
__global__ __launch_bounds__(256, 1) void attn_kernel(
    const __half* __restrict__ G, const float* __restrict__ SQ,
    const __half* __restrict__ H, const __half* __restrict__ HR,
    const float* __restrict__ tempp, const float* __restrict__ thetap,
    float* __restrict__ Out, int do_relu)
{
    __shared__ __align__(16) __half sK[64 * 72];    // G keys, pitch 72 (conflict-free ldmatrix)
    __shared__ __align__(16) __half sH[64 * 136];   // H tile, pitch 136
    __shared__ float sSq[64];

    const int tid  = threadIdx.x;
    const int lane = tid & 31;
    const int warp = tid >> 5;
    const int gid  = lane >> 2;     // 0..7
    const int qid  = lane & 3;      // 0..3
    const int rowbase = blockIdx.x * 128 + warp * 16;
    const int r0 = rowbase + gid, r1 = r0 + 8;

    const float t  = 1.0f + *tempp;
    const float th = 5.0f + *thetap;
    const float t2 = 2.0f * t;

    // Q fragments (A of m16n8k16), loaded straight from gmem
    uint32_t aq[4][4];
    const uint32_t* G32 = reinterpret_cast<const uint32_t*>(G);
    #pragma unroll
    for (int ks = 0; ks < 4; ks++) {
        int c0 = ks * 8 + qid;
        aq[ks][0] = G32[(size_t)r0 * 32 + c0];
        aq[ks][1] = G32[(size_t)r1 * 32 + c0];
        aq[ks][2] = G32[(size_t)r0 * 32 + c0 + 4];
        aq[ks][3] = G32[(size_t)r1 * 32 + c0 + 4];
    }
    const float ci0 = th - t * SQ[r0];
    const float ci1 = th - t * SQ[r1];

    float accO[16][4];
    #pragma unroll
    for (int i = 0; i < 16; i++)
        #pragma unroll
        for (int j = 0; j < 4; j++) accO[i][j] = 0.f;
    float rs0 = 0.f, rs1 = 0.f;

    const uint32_t skbase = (uint32_t)__cvta_generic_to_shared(sK);
    const uint32_t shbase = (uint32_t)__cvta_generic_to_shared(sH);

    for (int j0 = 0; j0 < NROWS; j0 += 64) {
        __syncthreads();
        {
            const uint4* srcK = reinterpret_cast<const uint4*>(G + (size_t)j0 * 64);
            #pragma unroll
            for (int i = tid; i < 512; i += 256) {
                int r = i >> 3, c = i & 7;
                *reinterpret_cast<uint4*>(sK + r * 72 + c * 8) = srcK[i];
            }
            const uint4* srcH = reinterpret_cast<const uint4*>(H + (size_t)j0 * 128);
            #pragma unroll
            for (int i = tid; i < 1024; i += 256) {
                int r = i >> 4, c = i & 15;
                *reinterpret_cast<uint4*>(sH + r * 136 + c * 8) = srcH[i];
            }
            if (tid < 64) sSq[tid] = SQ[j0 + tid];
        }
        __syncthreads();

        // ---- S = Gq @ Gk^T, then P = sigmoid(...) in fp16 A-fragment layout ----
        uint32_t pP[8][2];
        #pragma unroll
        for (int nb = 0; nb < 8; nb++) {
            float c4[4] = {0.f, 0.f, 0.f, 0.f};
            uint32_t b0, b1, b2, b3, b4, b5, b6, b7;
            uint32_t addr = skbase + ((nb * 8 + (lane & 7)) * 72 + (lane >> 3) * 8) * 2;
            ldsm4(b0, b1, b2, b3, addr);
            ldsm4(b4, b5, b6, b7, addr + 64);   // +32 halves = next 4 k-blocks
            mma_16816(c4, aq[0], b0, b1);
            mma_16816(c4, aq[1], b2, b3);
            mma_16816(c4, aq[2], b4, b5);
            mma_16816(c4, aq[3], b6, b7);

            float tsq0 = t * sSq[nb * 8 + qid * 2];
            float tsq1 = t * sSq[nb * 8 + qid * 2 + 1];
            float p00 = sigmoid_fast(fmaf(t2, c4[0], ci0 - tsq0));
            float p01 = sigmoid_fast(fmaf(t2, c4[1], ci0 - tsq1));
            float p10 = sigmoid_fast(fmaf(t2, c4[2], ci1 - tsq0));
            float p11 = sigmoid_fast(fmaf(t2, c4[3], ci1 - tsq1));

            __half2 ph0 = __floats2half2_rn(p00, p01);
            __half2 ph1 = __floats2half2_rn(p10, p11);
            // rowsum from the SAME fp16-rounded weights -> diag rounding cancels in ratio
            float2 pf0 = __half22float2(ph0);
            float2 pf1 = __half22float2(ph1);
            rs0 += pf0.x + pf0.y;
            rs1 += pf1.x + pf1.y;
            pP[nb][0] = *reinterpret_cast<uint32_t*>(&ph0);
            pP[nb][1] = *reinterpret_cast<uint32_t*>(&ph1);
        }

        // ---- O += P @ H ----
        #pragma unroll
        for (int ks = 0; ks < 4; ks++) {
            uint32_t ap[4] = { pP[2 * ks][0], pP[2 * ks][1], pP[2 * ks + 1][0], pP[2 * ks + 1][1] };
            #pragma unroll
            for (int np = 0; np < 8; np++) {
                uint32_t h0, h1, h2, h3;
                uint32_t addr = shbase +
                    ((ks * 16 + ((lane >> 3) & 1) * 8 + (lane & 7)) * 136 +
                     np * 16 + (lane >> 4) * 8) * 2;
                ldsm4t(h0, h1, h2, h3, addr);
                mma_16816(accO[2 * np],     ap, h0, h1);
                mma_16816(accO[2 * np + 1], ap, h2, h3);
            }
        }
    }

    // ---- epilogue: rowsum reduce, normalize, diag h-residual correction ----
    rs0 += __shfl_xor_sync(0xffffffffu, rs0, 1);
    rs0 += __shfl_xor_sync(0xffffffffu, rs0, 2);
    rs1 += __shfl_xor_sync(0xffffffffu, rs1, 1);
    rs1 += __shfl_xor_sync(0xffffffffu, rs1, 2);
    const float inv0 = 1.0f / rs0;
    const float inv1 = 1.0f / rs1;
    const float pd = 1.0f / (1.0f + expf(-th));   // precise diag weight estimate

    #pragma unroll
    for (int nb = 0; nb < 16; nb++) {
        int c0 = nb * 8 + qid * 2;
        __half2 hr0 = *reinterpret_cast<const __half2*>(HR + (size_t)r0 * 128 + c0);
        __half2 hr1 = *reinterpret_cast<const __half2*>(HR + (size_t)r1 * 128 + c0);
        float2 f0 = __half22float2(hr0);
        float2 f1 = __half22float2(hr1);
        float v00 = fmaf(pd, f0.x, accO[nb][0]) * inv0;
        float v01 = fmaf(pd, f0.y, accO[nb][1]) * inv0;
        float v10 = fmaf(pd, f1.x, accO[nb][2]) * inv1;
        float v11 = fmaf(pd, f1.y, accO[nb][3]) * inv1;
        if (do_relu) {
            v00 = fmaxf(v00, 0.f); v01 = fmaxf(v01, 0.f);
            v10 = fmaxf(v10, 0.f); v11 = fmaxf(v11, 0.f);
        }
        *reinterpret_cast<float2*>(Out + (size_t)r0 * 128 + c0) = make_float2(v00, v01);
        *reinterpret_cast<float2*>(Out + (size_t)r1 * 128 + c0) = make_float2(v10, v11);
    }
}

// ---------------- final projection (128->10) + softmax ----------------
__global__ __launch_bounds__(256) void out_kernel(
    const float* __restrict__ X, const float* __restrict__ W,
    const float* __restrict__ B, float* __restrict__ out)
{
    int gw = (blockIdx.x * blockDim.x + threadIdx.x) >> 5;
    int lane = threadIdx.x & 31;
    if (gw >= NROWS) return;
    const float* x = X + (size_t)gw * 128;
    float xv0 = x[lane], xv1 = x[lane + 32], xv2 = x[lane + 64], xv3 = x[lane + 96];
    float lg[10];
    #pragma unroll
    for (int c = 0; c < 10; c++) {
        float s = xv0 * W[lane * 10 + c] + xv1 * W[(lane + 32) * 10 + c]
                + xv2 * W[(lane + 64) * 10 + c] + xv3 * W[(lane + 96) * 10 + c];
        #pragma unroll
        for (int off = 16; off; off >>= 1) s += __shfl_xor_sync(0xffffffffu, s, off);
        lg[c] = s + B[c];
    }
    if (lane == 0) {
        float mx = lg[0];
        #pragma unroll
        for (int c = 1; c < 10; c++) mx = fmaxf(mx, lg[c]);
        float den = 0.f, e[10];
        #pragma unroll
        for (int c = 0; c < 10; c++) { e[c] = expf(lg[c] - mx); den += e[c]; }
        float inv = 1.0f / den;
        #pragma unroll
        for (int c = 0; c < 10; c++) out[(size_t)gw * 10 + c] = e[c] * inv;
    }
}

// ---------------- launch ----------------
extern "C" void kernel_launch(void* const* d_in, const int* in_sizes, int n_in,
                              void* d_out, int out_size)
{
    const float* feat   = (const float*)d_in[0];
    const float* gl_w0  = (const float*)d_in[1];
    const float* gl_b0  = (const float*)d_in[2];
    const float* gl_w1  = (const float*)d_in[3];
    const float* gl_b1  = (const float*)d_in[4];
    const float* gnn_w0 = (const float*)d_in[5];
    const float* gnn_b0 = (const float*)d_in[6];
    const float* gnn_w1 = (const float*)d_in[7];
    const float* gnn_b1 = (const float*)d_in[8];
    const float* out_w  = (const float*)d_in[9];
    const float* out_b  = (const float*)d_in[10];
    const float* temp   = (const float*)d_in[11];
    const float* theta  = (const float*)d_in[12];
    // d_in[13..17]: adj_matrix / index / mask inputs are dead in the reference.

    float*  Xp;  cudaGetSymbolAddress((void**)&Xp,  g_X);
    __half* Gp;  cudaGetSymbolAddress((void**)&Gp,  g_G);
    float*  SQp; cudaGetSymbolAddress((void**)&SQp, g_SQ);
    __half* Hp;  cudaGetSymbolAddress((void**)&Hp,  g_H);
    __half* HRp; cudaGetSymbolAddress((void**)&HRp, g_HR);

    // layer 1 (input = feat_matrix), relu on output
    proj_kernel<64,  true ><<<NROWS / 32, 256>>>(feat, gl_w0,  gl_b0,  Gp, nullptr, SQp);
    proj_kernel<128, false><<<NROWS / 32, 256>>>(feat, gnn_w0, gnn_b0, Hp, HRp, nullptr);
    attn_kernel<<<NROWS / 128, 256>>>(Gp, SQp, Hp, HRp, temp, theta, Xp, 1);

    // layer 2 (input = layer-1 output), no relu
    proj_kernel<64,  true ><<<NROWS / 32, 256>>>(Xp, gl_w1,  gl_b1,  Gp, nullptr, SQp);
    proj_kernel<128, false><<<NROWS / 32, 256>>>(Xp, gnn_w1, gnn_b1, Hp, HRp, nullptr);
    attn_kernel<<<NROWS / 128, 256>>>(Gp, SQp, Hp, HRp, temp, theta, Xp, 0);

    // output head + softmax
    out_kernel<<<NROWS * 32 / 256, 256>>>(Xp, out_w, out_b, (float*)d_out);
}

// round 8
// speedup vs baseline: 1.1534x; 1.1534x over previous
#include <cuda_runtime.h>
#include <cuda_fp16.h>
#include <stdint.h>

#define NROWS 16384
#define KSPLIT 8
#define TILES (128 * KSPLIT)
#define CHUNK (NROWS / KSPLIT)   // 2048 keys per chunk
#define NIT   (CHUNK / 64)       // 32 inner iterations

// ---------------- scratch (device globals; no allocation allowed) ----------------
__device__ float  g_X  [NROWS * 128];          // layer output / next-layer input
__device__ __half g_G  [NROWS * 64];           // graph-learn projection (fp16)
__device__ float  g_SQ [NROWS];                // |g16|^2
__device__ __half g_H  [NROWS * 128];          // gnn projection (fp16)
__device__ __half g_HR [NROWS * 128];          // fp32-fp16 residual of H
__device__ float  g_PO [(size_t)KSPLIT * NROWS * 128];  // partial O per keychunk
__device__ float  g_PRS[(size_t)KSPLIT * NROWS];        // partial rowsums

// ---------------- asm helpers ----------------
__device__ __forceinline__ void mma_16816(float (&c)[4], const uint32_t (&a)[4],
                                          uint32_t b0, uint32_t b1) {
    asm volatile(
        "mma.sync.aligned.m16n8k16.row.col.f32.f16.f16.f32 "
        "{%0,%1,%2,%3},{%4,%5,%6,%7},{%8,%9},{%0,%1,%2,%3};\n"
        : "+f"(c[0]), "+f"(c[1]), "+f"(c[2]), "+f"(c[3])
        : "r"(a[0]), "r"(a[1]), "r"(a[2]), "r"(a[3]), "r"(b0), "r"(b1));
}
__device__ __forceinline__ void ldsm4(uint32_t &r0, uint32_t &r1, uint32_t &r2, uint32_t &r3,
                                      uint32_t addr) {
    asm volatile("ldmatrix.sync.aligned.m8n8.x4.shared.b16 {%0,%1,%2,%3},[%4];\n"
                 : "=r"(r0), "=r"(r1), "=r"(r2), "=r"(r3) : "r"(addr));
}
__device__ __forceinline__ void ldsm4t(uint32_t &r0, uint32_t &r1, uint32_t &r2, uint32_t &r3,
                                       uint32_t addr) {
    asm volatile("ldmatrix.sync.aligned.m8n8.x4.trans.shared.b16 {%0,%1,%2,%3},[%4];\n"
                 : "=r"(r0), "=r"(r1), "=r"(r2), "=r"(r3) : "r"(addr));
}
__device__ __forceinline__ void cp16(uint32_t dst, const void* src) {
    asm volatile("cp.async.cg.shared.global [%0], [%1], 16;\n" :: "r"(dst), "l"(src));
}
#define CP_COMMIT() asm volatile("cp.async.commit_group;\n" ::: "memory")
#define CP_WAIT1()  asm volatile("cp.async.wait_group 1;\n" ::: "memory")

__device__ __forceinline__ float sigmoid_fast(float x) {
    // fp32: MUFU.EX2 + MUFU.RCP. abs err ~1e-6 — the fp16-arg tanh path (R2) was
    // the 7.4e-3 failure; sigmoid argument MUST stay fp32.
    return __fdividef(1.0f, 1.0f + __expf(-x));
}

// ---------------- projection kernels ----------------
// X[N,128] @ W[128,DOUT] + B.  GMODE: relu -> fp16 G + |g16|^2.
// !GMODE: fp16 H + fp16 residual (h32 - h16).
template<int DOUT, bool GMODE>
__global__ __launch_bounds__(256) void proj_kernel(
    const float* __restrict__ X, const float* __restrict__ W, const float* __restrict__ B,
    __half* __restrict__ outh, __half* __restrict__ outres, float* __restrict__ sq)
{
    constexpr int CS = DOUT / 32;
    __shared__ __align__(16) float Xs[32 * 132];
    __shared__ __align__(16) float Ws[32 * DOUT];

    const int tid  = threadIdx.x;
    const int lane = tid & 31;
    const int wy   = tid >> 5;
    const int rowbase = blockIdx.x * 32;

    #pragma unroll
    for (int i = tid; i < 32 * 32; i += 256) {
        int r = i >> 5, c = i & 31;
        ((float4*)(Xs + r * 132))[c] =
            ((const float4*)(X + (size_t)(rowbase + r) * 128))[c];
    }

    float acc[4][CS];
    #pragma unroll
    for (int rs = 0; rs < 4; rs++)
        #pragma unroll
        for (int cs = 0; cs < CS; cs++) acc[rs][cs] = 0.f;

    for (int kc = 0; kc < 128; kc += 32) {
        __syncthreads();
        #pragma unroll
        for (int i = tid; i < 32 * DOUT / 4; i += 256)
            ((float4*)Ws)[i] = ((const float4*)(W + (size_t)kc * DOUT))[i];
        __syncthreads();

        #pragma unroll
        for (int k4 = 0; k4 < 8; k4++) {
            float4 xv[4];
            #pragma unroll
            for (int rs = 0; rs < 4; rs++)
                xv[rs] = *(const float4*)(Xs + (wy + rs * 8) * 132 + kc + k4 * 4);
            #pragma unroll
            for (int kk = 0; kk < 4; kk++) {
                float wv[CS];
                if (CS == 4) {
                    float4 w4 = *(const float4*)(Ws + (k4 * 4 + kk) * DOUT + lane * 4);
                    wv[0] = w4.x; wv[1] = w4.y; wv[2] = w4.z; wv[3 % CS] = w4.w;
                } else {
                    float2 w2 = *(const float2*)(Ws + (k4 * 4 + kk) * DOUT + lane * 2);
                    wv[0] = w2.x; wv[1 % CS] = w2.y;
                }
                #pragma unroll
                for (int rs = 0; rs < 4; rs++) {
                    float xk = ((const float*)&xv[rs])[kk];
                    #pragma unroll
                    for (int cs = 0; cs < CS; cs++)
                        acc[rs][cs] = fmaf(xk, wv[cs], acc[rs][cs]);
                }
            }
        }
    }

    #pragma unroll
    for (int rs = 0; rs < 4; rs++) {
        int row = rowbase + wy + rs * 8;
        float ssq = 0.f;
        #pragma unroll
        for (int cs = 0; cs < CS; cs++) {
            int col = lane * CS + cs;
            float v = acc[rs][cs] + B[col];
            if (GMODE) v = fmaxf(v, 0.f);
            __half h = __float2half_rn(v);
            outh[(size_t)row * DOUT + col] = h;
            float vh = __half2float(h);
            if (GMODE) ssq += vh * vh;
            else       outres[(size_t)row * DOUT + col] = __float2half_rn(v - vh);
        }
        if (GMODE) {
            #pragma unroll
            for (int off = 16; off; off >>= 1) ssq += __shfl_xor_sync(0xffffffffu, ssq, off);
            if (lane == 0) sq[row] = ssq;
        }
    }
}

// ---------------- fused sigmoid-attention kernel (persistent, key-split) ----------------
// partialO[kc] += sigmoid(t*(2 g_i.g_j - sq_i - sq_j) + th) @ h ; partialRS[kc] += rowsum
// sigmoid in FP32 (EX2+RCP); only P is fp16-rounded (cancels in O/rowsum ratio).
// Tile = (rowblock of 128, keychunk of 2048). 148 persistent CTAs, static schedule.

// dynamic smem layout (bytes)
#define OFF_K0  0
#define OFF_K1  9216
#define OFF_H0  18432
#define OFF_H1  35840
#define OFF_SQ0 53248
#define OFF_SQ1 53504
#define SMEM_BYTES 53760

__global__ __launch_bounds__(256, 1) void attn_kernel(
    const __half* __restrict__ G, const float* __restrict__ SQ,
    const __half* __restrict__ H,
    const float* __restrict__ tempp, const float* __restrict__ thetap,
    float* __restrict__ PO, float* __restrict__ PRS)
{
    extern __shared__ __align__(16) char dsm[];
    const uint32_t smem_u32 = (uint32_t)__cvta_generic_to_shared(dsm);

    const int tid  = threadIdx.x;
    const int lane = tid & 31;
    const int warp = tid >> 5;
    const int gid  = lane >> 2;
    const int qid  = lane & 3;

    const float tt = 1.0f + *tempp;       // t
    const float th = 5.0f + *thetap;
    const float t2 = 2.0f * tt;
    const uint32_t ONES = 0x3C003C00u;

    const uint32_t* G32 = reinterpret_cast<const uint32_t*>(G);

    for (int t = blockIdx.x; t < TILES; t += gridDim.x) {
        const int rb = t & 127;
        const int kc = t >> 7;
        const int keybase = kc * CHUNK;
        const int rowbase = rb * 128 + warp * 16;
        const int r0 = rowbase + gid, r1 = r0 + 8;

        // Q fragments
        uint32_t aq[4][4];
        #pragma unroll
        for (int ks = 0; ks < 4; ks++) {
            int c0 = ks * 8 + qid;
            aq[ks][0] = G32[(size_t)r0 * 32 + c0];
            aq[ks][1] = G32[(size_t)r1 * 32 + c0];
            aq[ks][2] = G32[(size_t)r0 * 32 + c0 + 4];
            aq[ks][3] = G32[(size_t)r1 * 32 + c0 + 4];
        }
        const float ci0 = fmaf(-tt, SQ[r0], th);   // th - t*sq_i
        const float ci1 = fmaf(-tt, SQ[r1], th);

        float accO[16][4];
        #pragma unroll
        for (int i = 0; i < 16; i++)
            #pragma unroll
            for (int j = 0; j < 4; j++) accO[i][j] = 0.f;
        float rsacc[4] = {0.f, 0.f, 0.f, 0.f};

        // ---- async tile loader ----
        auto issue = [&](int it, int buf) {
            int j0 = keybase + it * 64;
            uint32_t kdst = smem_u32 + (buf ? OFF_K1 : OFF_K0);
            const char* ksrc = (const char*)(G + (size_t)j0 * 64);
            #pragma unroll
            for (int i = tid; i < 512; i += 256) {
                int r = i >> 3, c = i & 7;
                cp16(kdst + (r * 72 + c * 8) * 2, ksrc + i * 16);
            }
            uint32_t hdst = smem_u32 + (buf ? OFF_H1 : OFF_H0);
            const char* hsrc = (const char*)(H + (size_t)j0 * 128);
            #pragma unroll
            for (int i = tid; i < 1024; i += 256) {
                int r = i >> 4, c = i & 15;
                cp16(hdst + (r * 136 + c * 8) * 2, hsrc + i * 16);
            }
            if (tid < 16)
                cp16(smem_u32 + (buf ? OFF_SQ1 : OFF_SQ0) + tid * 16,
                     (const char*)(SQ + j0) + tid * 16);
        };

        issue(0, 0);
        CP_COMMIT();

        for (int it = 0; it < NIT; it++) {
            const int buf = it & 1;
            if (it + 1 < NIT) issue(it + 1, buf ^ 1);
            CP_COMMIT();
            CP_WAIT1();
            __syncthreads();

            const uint32_t skb = smem_u32 + (buf ? OFF_K1 : OFF_K0);
            const uint32_t shb = smem_u32 + (buf ? OFF_H1 : OFF_H0);
            const float* sqb = (const float*)(dsm + (buf ? OFF_SQ1 : OFF_SQ0));

            // ---- S = Gq @ Gk^T -> P = sigmoid (fp32) -> fp16 pack ----
            uint32_t pP[8][2];
            #pragma unroll
            for (int nb = 0; nb < 8; nb++) {
                float c4[4] = {0.f, 0.f, 0.f, 0.f};
                uint32_t b0, b1, b2, b3, b4, b5, b6, b7;
                uint32_t addr = skb + ((nb * 8 + (lane & 7)) * 72 + (lane >> 3) * 8) * 2;
                ldsm4(b0, b1, b2, b3, addr);
                ldsm4(b4, b5, b6, b7, addr + 64);
                mma_16816(c4, aq[0], b0, b1);
                mma_16816(c4, aq[1], b2, b3);
                mma_16816(c4, aq[2], b4, b5);
                mma_16816(c4, aq[3], b6, b7);

                float tsq0 = tt * sqb[nb * 8 + qid * 2];
                float tsq1 = tt * sqb[nb * 8 + qid * 2 + 1];
                float p00 = sigmoid_fast(fmaf(t2, c4[0], ci0 - tsq0));
                float p01 = sigmoid_fast(fmaf(t2, c4[1], ci0 - tsq1));
                float p10 = sigmoid_fast(fmaf(t2, c4[2], ci1 - tsq0));
                float p11 = sigmoid_fast(fmaf(t2, c4[3], ci1 - tsq1));

                __half2 ph0 = __floats2half2_rn(p00, p01);
                __half2 ph1 = __floats2half2_rn(p10, p11);
                pP[nb][0] = *reinterpret_cast<uint32_t*>(&ph0);
                pP[nb][1] = *reinterpret_cast<uint32_t*>(&ph1);
            }

            // ---- O += P @ H ; rowsum += P @ 1 (same fp16 P, fp32 accum) ----
            #pragma unroll
            for (int ks = 0; ks < 4; ks++) {
                uint32_t ap[4] = { pP[2*ks][0], pP[2*ks][1], pP[2*ks+1][0], pP[2*ks+1][1] };
                mma_16816(rsacc, ap, ONES, ONES);
                #pragma unroll
                for (int np = 0; np < 8; np++) {
                    uint32_t h0, h1, h2, h3;
                    uint32_t addr = shb +
                        ((ks * 16 + ((lane >> 3) & 1) * 8 + (lane & 7)) * 136 +
                         np * 16 + (lane >> 4) * 8) * 2;
                    ldsm4t(h0, h1, h2, h3, addr);
                    mma_16816(accO[2 * np],     ap, h0, h1);
                    mma_16816(accO[2 * np + 1], ap, h2, h3);
                }
            }
            __syncthreads();
        }

        // ---- store partial O and rowsums ----
        float* po = PO + (size_t)kc * NROWS * 128;
        #pragma unroll
        for (int nb = 0; nb < 16; nb++) {
            int c0 = nb * 8 + qid * 2;
            *(float2*)(po + (size_t)r0 * 128 + c0) = make_float2(accO[nb][0], accO[nb][1]);
            *(float2*)(po + (size_t)r1 * 128 + c0) = make_float2(accO[nb][2], accO[nb][3]);
        }
        if (qid == 0) {
            PRS[(size_t)kc * NROWS + r0] = rsacc[0];
            PRS[(size_t)kc * NROWS + r1] = rsacc[2];
        }
    }
}

// ---------------- combine: sum partials, diag residual, normalize, relu ----------------
__global__ __launch_bounds__(256) void combine_kernel(
    const float* __restrict__ PO, const float* __restrict__ PRS,
    const __half* __restrict__ HR, const float* __restrict__ thetap,
    float* __restrict__ X, int do_relu)
{
    const int row = blockIdx.x * 2 + (threadIdx.x >> 7);
    const int col = threadIdx.x & 127;
    const float th = 5.0f + *thetap;
    const float pd = 1.0f / (1.0f + expf(-th));

    float acc = 0.f, rs = 0.f;
    #pragma unroll
    for (int k = 0; k < KSPLIT; k++) {
        acc += PO[((size_t)k * NROWS + row) * 128 + col];
        rs  += PRS[(size_t)k * NROWS + row];
    }
    float hr = __half2float(HR[(size_t)row * 128 + col]);
    float v = fmaf(pd, hr, acc) / rs;
    if (do_relu) v = fmaxf(v, 0.f);
    X[(size_t)row * 128 + col] = v;
}

// ---------------- final projection (128->10) + softmax ----------------
__global__ __launch_bounds__(256) void out_kernel(
    const float* __restrict__ X, const float* __restrict__ W,
    const float* __restrict__ B, float* __restrict__ out)
{
    int gw = (blockIdx.x * blockDim.x + threadIdx.x) >> 5;
    int lane = threadIdx.x & 31;
    if (gw >= NROWS) return;
    const float* x = X + (size_t)gw * 128;
    float xv0 = x[lane], xv1 = x[lane + 32], xv2 = x[lane + 64], xv3 = x[lane + 96];
    float lg[10];
    #pragma unroll
    for (int c = 0; c < 10; c++) {
        float s = xv0 * W[lane * 10 + c] + xv1 * W[(lane + 32) * 10 + c]
                + xv2 * W[(lane + 64) * 10 + c] + xv3 * W[(lane + 96) * 10 + c];
        #pragma unroll
        for (int off = 16; off; off >>= 1) s += __shfl_xor_sync(0xffffffffu, s, off);
        lg[c] = s + B[c];
    }
    if (lane == 0) {
        float mx = lg[0];
        #pragma unroll
        for (int c = 1; c < 10; c++) mx = fmaxf(mx, lg[c]);
        float den = 0.f, e[10];
        #pragma unroll
        for (int c = 0; c < 10; c++) { e[c] = expf(lg[c] - mx); den += e[c]; }
        float inv = 1.0f / den;
        #pragma unroll
        for (int c = 0; c < 10; c++) out[(size_t)gw * 10 + c] = e[c] * inv;
    }
}

// ---------------- launch ----------------
extern "C" void kernel_launch(void* const* d_in, const int* in_sizes, int n_in,
                              void* d_out, int out_size)
{
    const float* feat   = (const float*)d_in[0];
    const float* gl_w0  = (const float*)d_in[1];
    const float* gl_b0  = (const float*)d_in[2];
    const float* gl_w1  = (const float*)d_in[3];
    const float* gl_b1  = (const float*)d_in[4];
    const float* gnn_w0 = (const float*)d_in[5];
    const float* gnn_b0 = (const float*)d_in[6];
    const float* gnn_w1 = (const float*)d_in[7];
    const float* gnn_b1 = (const float*)d_in[8];
    const float* out_w  = (const float*)d_in[9];
    const float* out_b  = (const float*)d_in[10];
    const float* temp   = (const float*)d_in[11];
    const float* theta  = (const float*)d_in[12];

    float*  Xp;  cudaGetSymbolAddress((void**)&Xp,  g_X);
    __half* Gp;  cudaGetSymbolAddress((void**)&Gp,  g_G);
    float*  SQp; cudaGetSymbolAddress((void**)&SQp, g_SQ);
    __half* Hp;  cudaGetSymbolAddress((void**)&Hp,  g_H);
    __half* HRp; cudaGetSymbolAddress((void**)&HRp, g_HR);
    float*  POp; cudaGetSymbolAddress((void**)&POp, g_PO);
    float*  PRSp;cudaGetSymbolAddress((void**)&PRSp,g_PRS);

    static bool attr_set = false;
    if (!attr_set) {
        cudaFuncSetAttribute(attn_kernel, cudaFuncAttributeMaxDynamicSharedMemorySize,
                             SMEM_BYTES);
        attr_set = true;
    }

    // layer 1
    proj_kernel<64,  true ><<<NROWS / 32, 256>>>(feat, gl_w0,  gl_b0,  Gp, nullptr, SQp);
    proj_kernel<128, false><<<NROWS / 32, 256>>>(feat, gnn_w0, gnn_b0, Hp, HRp, nullptr);
    attn_kernel<<<148, 256, SMEM_BYTES>>>(Gp, SQp, Hp, temp, theta, POp, PRSp);
    combine_kernel<<<NROWS / 2, 256>>>(POp, PRSp, HRp, theta, Xp, 1);

    // layer 2
    proj_kernel<64,  true ><<<NROWS / 32, 256>>>(Xp, gl_w1,  gl_b1,  Gp, nullptr, SQp);
    proj_kernel<128, false><<<NROWS / 32, 256>>>(Xp, gnn_w1, gnn_b1, Hp, HRp, nullptr);
    attn_kernel<<<148, 256, SMEM_BYTES>>>(Gp, SQp, Hp, temp, theta, POp, PRSp);
    combine_kernel<<<NROWS / 2, 256>>>(POp, PRSp, HRp, theta, Xp, 0);

    // output head + softmax
    out_kernel<<<NROWS * 32 / 256, 256>>>(Xp, out_w, out_b, (float*)d_out);
}